// round 3
// baseline (speedup 1.0000x reference)
#include <cuda_runtime.h>
#include <math.h>

#define B_SZ 64
#define N_SZ 1024
#define D_SZ 1024
#define M_SZ (B_SZ * N_SZ)

#define BM 128
#define BN 128
#define BK 8

__device__ float g_qh[B_SZ * D_SZ];
__device__ float g_scores[B_SZ * N_SZ];

// ---------------------------------------------------------------------------
// K1: qh[b,e] = sum_d h_t[b,d] * W_h[e,d]; also zero-init g_scores.
// One block per batch b. Warp per e (strided), lanes over d, shfl reduce.
// ---------------------------------------------------------------------------
__global__ void qh_kernel(const float* __restrict__ h_t,
                          const float* __restrict__ W_h) {
    __shared__ float sh[D_SZ];
    const int b = blockIdx.x;
    for (int d = threadIdx.x; d < D_SZ; d += blockDim.x)
        sh[d] = h_t[b * D_SZ + d];
    for (int n = threadIdx.x; n < N_SZ; n += blockDim.x)
        g_scores[b * N_SZ + n] = 0.f;
    __syncthreads();

    const int warp = threadIdx.x >> 5;
    const int lane = threadIdx.x & 31;
    for (int e = warp; e < D_SZ; e += 8) {
        const float* w = W_h + e * D_SZ;
        float s = 0.f;
        #pragma unroll 8
        for (int d = lane; d < D_SZ; d += 32)
            s += sh[d] * w[d];
        #pragma unroll
        for (int off = 16; off; off >>= 1)
            s += __shfl_xor_sync(0xffffffffu, s, off);
        if (lane == 0) g_qh[b * D_SZ + e] = s;
    }
}

// ---------------------------------------------------------------------------
// K2: fused score GEMM.
// scores[m] += sum over e-tile of v[e]*tanh(qh[b,e] + sum_d keys[m,d]*W_k[e,d])
// 128x128 tile, BK=8, 256 threads, 8x8 microtile using packed fma.rn.f32x2.
// Fragment cols: c = 32*j + 2*tx  (conflict-free LDS.64 b-pair loads).
// ---------------------------------------------------------------------------
#define FFMA2(c, a, b) \
    asm("fma.rn.f32x2 %0, %1, %2, %0;" : "+l"(c) : "l"(a), "l"(b))

__global__ void __launch_bounds__(256, 2)
score_gemm(const float* __restrict__ keys,
           const float* __restrict__ W_k,
           const float* __restrict__ v) {
    __shared__ float As[BK][BM + 4];
    __shared__ float Bs[BK][BN + 4];
    __shared__ float sQ[BN];
    __shared__ float sV[BN];

    const int tid = threadIdx.x;
    const int tx  = tid & 15;      // 0..15  (column group)
    const int ty  = tid >> 4;      // 0..15  (row group)
    const int m0  = blockIdx.y * BM;   // global row base (b*1024+n flattened)
    const int e0  = blockIdx.x * BN;   // global e base

    // global staging indices: one float4 per thread per matrix per K-chunk
    const int lrow = tid >> 1;         // 0..127
    const int lk   = (tid & 1) * 4;    // 0 or 4

    const float* aptr = keys + (size_t)(m0 + lrow) * D_SZ + lk;
    const float* bptr = W_k  + (size_t)(e0 + lrow) * D_SZ + lk;

    unsigned long long acc[8][4];
    #pragma unroll
    for (int i = 0; i < 8; i++)
        #pragma unroll
        for (int j = 0; j < 4; j++)
            acc[i][j] = 0ull;

    float4 afrag = *(const float4*)aptr;
    float4 bfrag = *(const float4*)bptr;

    const int tm0 = ty * 8;
    const int nkb = D_SZ / BK;  // 128

    for (int kb = 0; kb < nkb; kb++) {
        // commit staged tile (transposed: [k][row])
        As[lk + 0][lrow] = afrag.x;  As[lk + 1][lrow] = afrag.y;
        As[lk + 2][lrow] = afrag.z;  As[lk + 3][lrow] = afrag.w;
        Bs[lk + 0][lrow] = bfrag.x;  Bs[lk + 1][lrow] = bfrag.y;
        Bs[lk + 2][lrow] = bfrag.z;  Bs[lk + 3][lrow] = bfrag.w;
        __syncthreads();

        // prefetch next chunk (latency hidden under compute)
        if (kb + 1 < nkb) {
            afrag = *(const float4*)(aptr + (kb + 1) * BK);
            bfrag = *(const float4*)(bptr + (kb + 1) * BK);
        }

        #pragma unroll
        for (int k = 0; k < BK; k++) {
            const unsigned long long* brow =
                (const unsigned long long*)(&Bs[k][0]);
            unsigned long long b0 = brow[tx];
            unsigned long long b1 = brow[tx + 16];
            unsigned long long b2 = brow[tx + 32];
            unsigned long long b3 = brow[tx + 48];

            float4 a03 = *(const float4*)(&As[k][tm0]);
            float4 a47 = *(const float4*)(&As[k][tm0 + 4]);
            float av[8] = {a03.x, a03.y, a03.z, a03.w,
                           a47.x, a47.y, a47.z, a47.w};
            #pragma unroll
            for (int i = 0; i < 8; i++) {
                unsigned long long ap;
                unsigned int ai = __float_as_uint(av[i]);
                asm("mov.b64 %0, {%1, %1};" : "=l"(ap) : "r"(ai));
                FFMA2(acc[i][0], ap, b0);
                FFMA2(acc[i][1], ap, b1);
                FFMA2(acc[i][2], ap, b2);
                FFMA2(acc[i][3], ap, b3);
            }
        }
        __syncthreads();
    }

    // epilogue: tanh(kh + qh) . v  reduced over the 128-wide e-tile
    const int bidx = m0 >> 10;  // batch index (BM=128 divides N=1024)
    for (int c = tid; c < BN; c += 256) {
        sQ[c] = g_qh[bidx * D_SZ + e0 + c];
        sV[c] = v[e0 + c];
    }
    __syncthreads();

    const int lane = tid & 31;
    #pragma unroll
    for (int i = 0; i < 8; i++) {
        float psum = 0.f;
        #pragma unroll
        for (int j = 0; j < 4; j++) {
            float lo = __uint_as_float((unsigned)(acc[i][j] & 0xffffffffull));
            float hi = __uint_as_float((unsigned)(acc[i][j] >> 32));
            const int c = 32 * j + 2 * tx;
            psum += sV[c]     * tanhf(lo + sQ[c]);
            psum += sV[c + 1] * tanhf(hi + sQ[c + 1]);
        }
        // reduce over the 16 tx lanes (xor<=8 stays within each half-warp)
        #pragma unroll
        for (int off = 8; off; off >>= 1)
            psum += __shfl_xor_sync(0xffffffffu, psum, off);
        if ((lane & 15) == 0)
            atomicAdd(&g_scores[m0 + tm0 + i], psum);
    }
}

// ---------------------------------------------------------------------------
// K3: row softmax of scores -> alpha (written straight into d_out region)
// ---------------------------------------------------------------------------
__global__ void softmax_kernel(float* __restrict__ alpha) {
    const int b = blockIdx.x;
    const int tid = threadIdx.x;
    __shared__ float red[8];
    __shared__ float bcast;

    float x[4];
    float m = -1e30f;
    #pragma unroll
    for (int i = 0; i < 4; i++) {
        x[i] = g_scores[b * N_SZ + tid + i * 256];
        m = fmaxf(m, x[i]);
    }
    #pragma unroll
    for (int off = 16; off; off >>= 1)
        m = fmaxf(m, __shfl_xor_sync(0xffffffffu, m, off));
    if ((tid & 31) == 0) red[tid >> 5] = m;
    __syncthreads();
    if (tid == 0) {
        float mm = red[0];
        for (int w = 1; w < 8; w++) mm = fmaxf(mm, red[w]);
        bcast = mm;
    }
    __syncthreads();
    m = bcast;

    float s = 0.f;
    #pragma unroll
    for (int i = 0; i < 4; i++) {
        x[i] = expf(x[i] - m);
        s += x[i];
    }
    #pragma unroll
    for (int off = 16; off; off >>= 1)
        s += __shfl_xor_sync(0xffffffffu, s, off);
    __syncthreads();
    if ((tid & 31) == 0) red[tid >> 5] = s;
    __syncthreads();
    if (tid == 0) {
        float ss = red[0];
        for (int w = 1; w < 8; w++) ss += red[w];
        bcast = ss;
    }
    __syncthreads();
    const float inv = 1.f / bcast;
    #pragma unroll
    for (int i = 0; i < 4; i++)
        alpha[b * N_SZ + tid + i * 256] = x[i] * inv;
}

// ---------------------------------------------------------------------------
// K4: context[b,d] = sum_n alpha[b,n] * keys[b,n,d]   (memory-bound)
// ---------------------------------------------------------------------------
__global__ void context_kernel(const float* __restrict__ keys,
                               const float* __restrict__ alpha,
                               float* __restrict__ ctx) {
    const int b = blockIdx.y;
    const int d = blockIdx.x * 256 + threadIdx.x;
    const float* kb = keys + (size_t)b * N_SZ * D_SZ + d;
    const float* ab = alpha + b * N_SZ;
    float acc = 0.f;
    #pragma unroll 8
    for (int n = 0; n < N_SZ; n++)
        acc += ab[n] * kb[(size_t)n * D_SZ];
    ctx[b * D_SZ + d] = acc;
}

// ---------------------------------------------------------------------------
extern "C" void kernel_launch(void* const* d_in, const int* in_sizes, int n_in,
                              void* d_out, int out_size) {
    const float* h_t  = (const float*)d_in[0];
    const float* keys = (const float*)d_in[1];
    const float* W_h  = (const float*)d_in[2];
    const float* W_k  = (const float*)d_in[3];
    const float* v    = (const float*)d_in[4];

    float* out   = (float*)d_out;
    float* ctx   = out;                  // context [64,1024]
    float* alpha = out + B_SZ * N_SZ;    // alpha   [64,1024]

    qh_kernel<<<B_SZ, 256>>>(h_t, W_h);
    score_gemm<<<dim3(N_SZ / BN, M_SZ / BM), 256>>>(keys, W_k, v);
    softmax_kernel<<<B_SZ, 256>>>(alpha);
    context_kernel<<<dim3(D_SZ / 256, B_SZ), 256>>>(keys, alpha, ctx);
}

// round 4
// speedup vs baseline: 1.0002x; 1.0002x over previous
#include <cuda_runtime.h>
#include <math.h>

#define B_SZ 64
#define N_SZ 1024
#define D_SZ 1024
#define M_SZ (B_SZ * N_SZ)

#define BM 128
#define BN 128
#define BK 8

__device__ float g_qh[B_SZ * D_SZ];
__device__ float g_scores[B_SZ * N_SZ];

// ---------------------------------------------------------------------------
// K1: qh[b,e] = sum_d h_t[b,d] * W_h[e,d]; also zero-init g_scores.
// One block per batch b. Warp per e (strided), lanes over d, shfl reduce.
// ---------------------------------------------------------------------------
__global__ void qh_kernel(const float* __restrict__ h_t,
                          const float* __restrict__ W_h) {
    __shared__ float sh[D_SZ];
    const int b = blockIdx.x;
    for (int d = threadIdx.x; d < D_SZ; d += blockDim.x)
        sh[d] = h_t[b * D_SZ + d];
    for (int n = threadIdx.x; n < N_SZ; n += blockDim.x)
        g_scores[b * N_SZ + n] = 0.f;
    __syncthreads();

    const int warp = threadIdx.x >> 5;
    const int lane = threadIdx.x & 31;
    for (int e = warp; e < D_SZ; e += 8) {
        const float* w = W_h + e * D_SZ;
        float s = 0.f;
        #pragma unroll 8
        for (int d = lane; d < D_SZ; d += 32)
            s += sh[d] * w[d];
        #pragma unroll
        for (int off = 16; off; off >>= 1)
            s += __shfl_xor_sync(0xffffffffu, s, off);
        if (lane == 0) g_qh[b * D_SZ + e] = s;
    }
}

// ---------------------------------------------------------------------------
// K2: fused score GEMM.
// scores[m] += sum over e-tile of v[e]*tanh(qh[b,e] + sum_d keys[m,d]*W_k[e,d])
// 128x128 tile, BK=8, 256 threads, 8x8 microtile using packed fma.rn.f32x2.
// Fragment cols: c = 32*j + 2*tx  (conflict-free LDS.64 b-pair loads).
// ---------------------------------------------------------------------------
#define FFMA2(c, a, b) \
    asm("fma.rn.f32x2 %0, %1, %2, %0;" : "+l"(c) : "l"(a), "l"(b))

__global__ void __launch_bounds__(256, 2)
score_gemm(const float* __restrict__ keys,
           const float* __restrict__ W_k,
           const float* __restrict__ v) {
    __shared__ float As[BK][BM + 4];
    __shared__ float Bs[BK][BN + 4];
    __shared__ float sQ[BN];
    __shared__ float sV[BN];

    const int tid = threadIdx.x;
    const int tx  = tid & 15;      // 0..15  (column group)
    const int ty  = tid >> 4;      // 0..15  (row group)
    const int m0  = blockIdx.y * BM;   // global row base (b*1024+n flattened)
    const int e0  = blockIdx.x * BN;   // global e base

    // global staging indices: one float4 per thread per matrix per K-chunk
    const int lrow = tid >> 1;         // 0..127
    const int lk   = (tid & 1) * 4;    // 0 or 4

    const float* aptr = keys + (size_t)(m0 + lrow) * D_SZ + lk;
    const float* bptr = W_k  + (size_t)(e0 + lrow) * D_SZ + lk;

    unsigned long long acc[8][4];
    #pragma unroll
    for (int i = 0; i < 8; i++)
        #pragma unroll
        for (int j = 0; j < 4; j++)
            acc[i][j] = 0ull;

    float4 afrag = *(const float4*)aptr;
    float4 bfrag = *(const float4*)bptr;

    const int tm0 = ty * 8;
    const int nkb = D_SZ / BK;  // 128

    for (int kb = 0; kb < nkb; kb++) {
        // commit staged tile (transposed: [k][row])
        As[lk + 0][lrow] = afrag.x;  As[lk + 1][lrow] = afrag.y;
        As[lk + 2][lrow] = afrag.z;  As[lk + 3][lrow] = afrag.w;
        Bs[lk + 0][lrow] = bfrag.x;  Bs[lk + 1][lrow] = bfrag.y;
        Bs[lk + 2][lrow] = bfrag.z;  Bs[lk + 3][lrow] = bfrag.w;
        __syncthreads();

        // prefetch next chunk (latency hidden under compute)
        if (kb + 1 < nkb) {
            afrag = *(const float4*)(aptr + (kb + 1) * BK);
            bfrag = *(const float4*)(bptr + (kb + 1) * BK);
        }

        #pragma unroll
        for (int k = 0; k < BK; k++) {
            const unsigned long long* brow =
                (const unsigned long long*)(&Bs[k][0]);
            unsigned long long b0 = brow[tx];
            unsigned long long b1 = brow[tx + 16];
            unsigned long long b2 = brow[tx + 32];
            unsigned long long b3 = brow[tx + 48];

            float4 a03 = *(const float4*)(&As[k][tm0]);
            float4 a47 = *(const float4*)(&As[k][tm0 + 4]);
            float av[8] = {a03.x, a03.y, a03.z, a03.w,
                           a47.x, a47.y, a47.z, a47.w};
            #pragma unroll
            for (int i = 0; i < 8; i++) {
                unsigned long long ap;
                unsigned int ai = __float_as_uint(av[i]);
                asm("mov.b64 %0, {%1, %1};" : "=l"(ap) : "r"(ai));
                FFMA2(acc[i][0], ap, b0);
                FFMA2(acc[i][1], ap, b1);
                FFMA2(acc[i][2], ap, b2);
                FFMA2(acc[i][3], ap, b3);
            }
        }
        __syncthreads();
    }

    // epilogue: tanh(kh + qh) . v  reduced over the 128-wide e-tile
    const int bidx = m0 >> 10;  // batch index (BM=128 divides N=1024)
    for (int c = tid; c < BN; c += 256) {
        sQ[c] = g_qh[bidx * D_SZ + e0 + c];
        sV[c] = v[e0 + c];
    }
    __syncthreads();

    const int lane = tid & 31;
    #pragma unroll
    for (int i = 0; i < 8; i++) {
        float psum = 0.f;
        #pragma unroll
        for (int j = 0; j < 4; j++) {
            float lo = __uint_as_float((unsigned)(acc[i][j] & 0xffffffffull));
            float hi = __uint_as_float((unsigned)(acc[i][j] >> 32));
            const int c = 32 * j + 2 * tx;
            psum += sV[c]     * tanhf(lo + sQ[c]);
            psum += sV[c + 1] * tanhf(hi + sQ[c + 1]);
        }
        // reduce over the 16 tx lanes (xor<=8 stays within each half-warp)
        #pragma unroll
        for (int off = 8; off; off >>= 1)
            psum += __shfl_xor_sync(0xffffffffu, psum, off);
        if ((lane & 15) == 0)
            atomicAdd(&g_scores[m0 + tm0 + i], psum);
    }
}

// ---------------------------------------------------------------------------
// K3: row softmax of scores -> alpha (written straight into d_out region)
// ---------------------------------------------------------------------------
__global__ void softmax_kernel(float* __restrict__ alpha) {
    const int b = blockIdx.x;
    const int tid = threadIdx.x;
    __shared__ float red[8];
    __shared__ float bcast;

    float x[4];
    float m = -1e30f;
    #pragma unroll
    for (int i = 0; i < 4; i++) {
        x[i] = g_scores[b * N_SZ + tid + i * 256];
        m = fmaxf(m, x[i]);
    }
    #pragma unroll
    for (int off = 16; off; off >>= 1)
        m = fmaxf(m, __shfl_xor_sync(0xffffffffu, m, off));
    if ((tid & 31) == 0) red[tid >> 5] = m;
    __syncthreads();
    if (tid == 0) {
        float mm = red[0];
        for (int w = 1; w < 8; w++) mm = fmaxf(mm, red[w]);
        bcast = mm;
    }
    __syncthreads();
    m = bcast;

    float s = 0.f;
    #pragma unroll
    for (int i = 0; i < 4; i++) {
        x[i] = expf(x[i] - m);
        s += x[i];
    }
    #pragma unroll
    for (int off = 16; off; off >>= 1)
        s += __shfl_xor_sync(0xffffffffu, s, off);
    __syncthreads();
    if ((tid & 31) == 0) red[tid >> 5] = s;
    __syncthreads();
    if (tid == 0) {
        float ss = red[0];
        for (int w = 1; w < 8; w++) ss += red[w];
        bcast = ss;
    }
    __syncthreads();
    const float inv = 1.f / bcast;
    #pragma unroll
    for (int i = 0; i < 4; i++)
        alpha[b * N_SZ + tid + i * 256] = x[i] * inv;
}

// ---------------------------------------------------------------------------
// K4: context[b,d] = sum_n alpha[b,n] * keys[b,n,d]   (memory-bound)
// ---------------------------------------------------------------------------
__global__ void context_kernel(const float* __restrict__ keys,
                               const float* __restrict__ alpha,
                               float* __restrict__ ctx) {
    const int b = blockIdx.y;
    const int d = blockIdx.x * 256 + threadIdx.x;
    const float* kb = keys + (size_t)b * N_SZ * D_SZ + d;
    const float* ab = alpha + b * N_SZ;
    float acc = 0.f;
    #pragma unroll 8
    for (int n = 0; n < N_SZ; n++)
        acc += ab[n] * kb[(size_t)n * D_SZ];
    ctx[b * D_SZ + d] = acc;
}

// ---------------------------------------------------------------------------
extern "C" void kernel_launch(void* const* d_in, const int* in_sizes, int n_in,
                              void* d_out, int out_size) {
    const float* h_t  = (const float*)d_in[0];
    const float* keys = (const float*)d_in[1];
    const float* W_h  = (const float*)d_in[2];
    const float* W_k  = (const float*)d_in[3];
    const float* v    = (const float*)d_in[4];

    float* out   = (float*)d_out;
    float* ctx   = out;                  // context [64,1024]
    float* alpha = out + B_SZ * N_SZ;    // alpha   [64,1024]

    qh_kernel<<<B_SZ, 256>>>(h_t, W_h);
    score_gemm<<<dim3(N_SZ / BN, M_SZ / BM), 256>>>(keys, W_k, v);
    softmax_kernel<<<B_SZ, 256>>>(alpha);
    context_kernel<<<dim3(D_SZ / 256, B_SZ), 256>>>(keys, alpha, ctx);
}

// round 8
// speedup vs baseline: 2.7322x; 2.7316x over previous
#include <cuda_runtime.h>
#include <math.h>

#define B_SZ 64
#define N_SZ 1024
#define D_SZ 1024
#define M_SZ (B_SZ * N_SZ)

__device__ float g_qh[B_SZ * D_SZ];
__device__ float g_part[4 * M_SZ];   // per-e-tile score partials

// ---------------- helpers --------------------------------------------------
__device__ __forceinline__ float tanh_fast(float x) {
    // tanh(x) = 1 - 2/(exp(2x)+1), via ex2/rcp approx (~1e-6 rel)
    float e;
    asm("ex2.approx.f32 %0, %1;" : "=f"(e) : "f"(x * 2.885390082f));
    float r;
    asm("rcp.approx.f32 %0, %1;" : "=f"(r) : "f"(e + 1.0f));
    return fmaf(-2.0f, r, 1.0f);
}
__device__ __forceinline__ unsigned cvt_tf32(float x) {
    unsigned u;
    asm("cvt.rna.tf32.f32 %0, %1;" : "=r"(u) : "f"(x));
    return u;
}
__device__ __forceinline__ uint4 cvt4(float4 v) {
    uint4 u;
    u.x = cvt_tf32(v.x); u.y = cvt_tf32(v.y);
    u.z = cvt_tf32(v.z); u.w = cvt_tf32(v.w);
    return u;
}
#define MMA_TF32(c, a, b0, b1) \
    asm volatile("mma.sync.aligned.m16n8k8.row.col.f32.tf32.tf32.f32 " \
        "{%0,%1,%2,%3}, {%4,%5,%6,%7}, {%8,%9}, {%0,%1,%2,%3};" \
        : "+f"((c)[0]), "+f"((c)[1]), "+f"((c)[2]), "+f"((c)[3]) \
        : "r"((a)[0]), "r"((a)[1]), "r"((a)[2]), "r"((a)[3]), \
          "r"(b0), "r"(b1))

// ---------------------------------------------------------------------------
// K1: qh[b,e] = h_t[b,:].W_h[e,:] (fp32); zero-init ctx slice.
// grid (4 e-slices, 64 b), 256 threads
// ---------------------------------------------------------------------------
__global__ void qh_kernel(const float* __restrict__ h_t,
                          const float* __restrict__ W_h,
                          float* __restrict__ ctx) {
    __shared__ float sh[D_SZ];
    const int b = blockIdx.y, es = blockIdx.x * 256;
    for (int d = threadIdx.x; d < D_SZ; d += 256)
        sh[d] = h_t[b * D_SZ + d];
    ctx[b * D_SZ + es + threadIdx.x] = 0.f;
    __syncthreads();
    const int warp = threadIdx.x >> 5, lane = threadIdx.x & 31;
    for (int e = es + warp; e < es + 256; e += 8) {
        const float* w = W_h + (size_t)e * D_SZ;
        float s = 0.f;
        #pragma unroll 8
        for (int d = lane; d < D_SZ; d += 32) s += sh[d] * w[d];
        #pragma unroll
        for (int off = 16; off; off >>= 1)
            s += __shfl_xor_sync(0xffffffffu, s, off);
        if (lane == 0) g_qh[b * D_SZ + e] = s;
    }
}

// ---------------------------------------------------------------------------
// K2: fused score GEMM on legacy tensor path (mma.sync tf32).
// Tile 128m x 256e per CTA, 16 warps (4m x 4e), warp tile 32m x 64e.
// k-chunk 32, double-buffered SMEM, pitch-36 rows (conflict-free frags).
// Epilogue: scores_part = sum_e v[e]*tanh(acc + qh[e]) per row.
// ---------------------------------------------------------------------------
#define AW 4608                    // 128*36 words
#define BW 9216                    // 256*36 words
#define STAGE_W (AW + BW)          // 13824 words
#define SQ_W (2 * STAGE_W)         // 27648
#define SV_W (SQ_W + 256)
#define SP_W (SV_W + 256)
#define TOT_W (SP_W + 128)         // 28288 words = 113152 bytes

__global__ void __launch_bounds__(512, 1)
score_tc(const float* __restrict__ keys,
         const float* __restrict__ W_k,
         const float* __restrict__ v) {
    extern __shared__ float sm[];
    const int tid = threadIdx.x;
    const int lane = tid & 31, warp = tid >> 5;
    const int g = lane >> 2, tg = lane & 3;       // fragment coords
    const int mw = warp & 3, ew = warp >> 2;      // warp grid 4m x 4e
    const int et = blockIdx.x, e0 = et * 256;
    const int m0 = blockIdx.y * 128, batch = m0 >> 10;

    // staging geometry: thread owns row (tid>>3) in each 64-row group,
    // float4 #(tid&7) of the 32-float k-chunk.
    const int srow = tid >> 3;
    const int kg4 = (tid & 7) * 4;
    const float* aR0 = keys + (size_t)(m0 + srow) * D_SZ + kg4;
    const float* aR1 = keys + (size_t)(m0 + 64 + srow) * D_SZ + kg4;
    const float* bR0 = W_k + (size_t)(e0 + srow) * D_SZ + kg4;
    const float* bR1 = W_k + (size_t)(e0 + 64 + srow) * D_SZ + kg4;
    const float* bR2 = W_k + (size_t)(e0 + 128 + srow) * D_SZ + kg4;
    const float* bR3 = W_k + (size_t)(e0 + 192 + srow) * D_SZ + kg4;
    const int wA0 = srow * 36 + kg4;              // word offsets (16B aligned)
    const int wA1 = (srow + 64) * 36 + kg4;

    if (tid < 128) sm[SP_W + tid] = 0.f;
    if (tid < 256) sm[SQ_W + tid] = g_qh[batch * D_SZ + e0 + tid];
    else           sm[SV_W + tid - 256] = v[e0 + tid - 256];

    float acc[2][8][4];
    #pragma unroll
    for (int mt = 0; mt < 2; mt++)
        #pragma unroll
        for (int nt = 0; nt < 8; nt++)
            #pragma unroll
            for (int i = 0; i < 4; i++) acc[mt][nt][i] = 0.f;

    // prologue: chunk 0 -> stage 0
    float4 ra0 = *(const float4*)aR0, ra1 = *(const float4*)aR1;
    float4 rb0 = *(const float4*)bR0, rb1 = *(const float4*)bR1;
    float4 rb2 = *(const float4*)bR2, rb3 = *(const float4*)bR3;
    *(uint4*)(sm + wA0) = cvt4(ra0);
    *(uint4*)(sm + wA1) = cvt4(ra1);
    *(uint4*)(sm + AW + wA0) = cvt4(rb0);
    *(uint4*)(sm + AW + wA1) = cvt4(rb1);
    *(uint4*)(sm + AW + wA0 + 128 * 36) = cvt4(rb2);
    *(uint4*)(sm + AW + wA1 + 128 * 36) = cvt4(rb3);
    __syncthreads();

    const int aBase0 = (mw * 32 + g) * 36 + tg;        // mt=0 row g
    const int bBase  = (ew * 64 + g) * 36 + tg;

    for (int kb = 0; kb < 32; kb++) {
        const int s = kb & 1;
        if (kb < 31) {                                  // prefetch next chunk
            const int ko = (kb + 1) * 32;
            ra0 = *(const float4*)(aR0 + ko); ra1 = *(const float4*)(aR1 + ko);
            rb0 = *(const float4*)(bR0 + ko); rb1 = *(const float4*)(bR1 + ko);
            rb2 = *(const float4*)(bR2 + ko); rb3 = *(const float4*)(bR3 + ko);
        }
        // compute on stage s
        {
            const unsigned* uA = (const unsigned*)(sm + s * STAGE_W);
            const unsigned* uB = uA + AW;
            #pragma unroll
            for (int ks = 0; ks < 4; ks++) {
                const int ak = ks * 8;
                unsigned a[2][4];
                #pragma unroll
                for (int mt = 0; mt < 2; mt++) {
                    const int r = aBase0 + mt * 16 * 36 + ak;
                    a[mt][0] = uA[r];
                    a[mt][1] = uA[r + 8 * 36];
                    a[mt][2] = uA[r + 4];
                    a[mt][3] = uA[r + 8 * 36 + 4];
                }
                #pragma unroll
                for (int nt = 0; nt < 8; nt++) {
                    const int bo = bBase + nt * 8 * 36 + ak;
                    unsigned b0 = uB[bo];
                    unsigned b1 = uB[bo + 4];
                    MMA_TF32(acc[0][nt], a[0], b0, b1);
                    MMA_TF32(acc[1][nt], a[1], b0, b1);
                }
            }
        }
        if (kb < 31) {                                  // stage s^1 (safe: last
            float* st = sm + (s ^ 1) * STAGE_W;         // read ended at kb-1)
            *(uint4*)(st + wA0) = cvt4(ra0);
            *(uint4*)(st + wA1) = cvt4(ra1);
            *(uint4*)(st + AW + wA0) = cvt4(rb0);
            *(uint4*)(st + AW + wA1) = cvt4(rb1);
            *(uint4*)(st + AW + wA0 + 128 * 36) = cvt4(rb2);
            *(uint4*)(st + AW + wA1 + 128 * 36) = cvt4(rb3);
        }
        __syncthreads();
    }

    // epilogue: per-row partial of sum_e v[e]*tanh(acc + qh[e])
    const float* sQ = sm + SQ_W;
    const float* sV = sm + SV_W;
    #pragma unroll
    for (int mt = 0; mt < 2; mt++) {
        float s0 = 0.f, s1 = 0.f;
        #pragma unroll
        for (int nt = 0; nt < 8; nt++) {
            const int cb = ew * 64 + nt * 8 + 2 * tg;
            const float q0 = sQ[cb], q1 = sQ[cb + 1];
            const float v0 = sV[cb], v1 = sV[cb + 1];
            s0 += v0 * tanh_fast(acc[mt][nt][0] + q0)
                + v1 * tanh_fast(acc[mt][nt][1] + q1);
            s1 += v0 * tanh_fast(acc[mt][nt][2] + q0)
                + v1 * tanh_fast(acc[mt][nt][3] + q1);
        }
        #pragma unroll
        for (int off = 1; off <= 2; off <<= 1) {
            s0 += __shfl_xor_sync(0xffffffffu, s0, off);
            s1 += __shfl_xor_sync(0xffffffffu, s1, off);
        }
        if (tg == 0) {
            atomicAdd(&sm[SP_W + mw * 32 + mt * 16 + g], s0);
            atomicAdd(&sm[SP_W + mw * 32 + mt * 16 + 8 + g], s1);
        }
    }
    __syncthreads();
    if (tid < 128)
        g_part[et * M_SZ + m0 + tid] = sm[SP_W + tid];
}

// ---------------------------------------------------------------------------
// K3: softmax over summed partials -> alpha
// ---------------------------------------------------------------------------
__global__ void softmax_kernel(float* __restrict__ alpha) {
    const int b = blockIdx.x, tid = threadIdx.x;
    __shared__ float red[8];
    __shared__ float bcast;
    float x[4]; float m = -1e30f;
    #pragma unroll
    for (int i = 0; i < 4; i++) {
        const int idx = b * N_SZ + tid + i * 256;
        x[i] = g_part[idx] + g_part[M_SZ + idx]
             + g_part[2 * M_SZ + idx] + g_part[3 * M_SZ + idx];
        m = fmaxf(m, x[i]);
    }
    #pragma unroll
    for (int off = 16; off; off >>= 1)
        m = fmaxf(m, __shfl_xor_sync(0xffffffffu, m, off));
    if ((tid & 31) == 0) red[tid >> 5] = m;
    __syncthreads();
    if (tid == 0) {
        float mm = red[0];
        for (int w = 1; w < 8; w++) mm = fmaxf(mm, red[w]);
        bcast = mm;
    }
    __syncthreads();
    m = bcast;
    float s = 0.f;
    #pragma unroll
    for (int i = 0; i < 4; i++) { x[i] = expf(x[i] - m); s += x[i]; }
    #pragma unroll
    for (int off = 16; off; off >>= 1)
        s += __shfl_xor_sync(0xffffffffu, s, off);
    __syncthreads();
    if ((tid & 31) == 0) red[tid >> 5] = s;
    __syncthreads();
    if (tid == 0) {
        float ss = red[0];
        for (int w = 1; w < 8; w++) ss += red[w];
        bcast = ss;
    }
    __syncthreads();
    const float inv = 1.f / bcast;
    #pragma unroll
    for (int i = 0; i < 4; i++)
        alpha[b * N_SZ + tid + i * 256] = x[i] * inv;
}

// ---------------------------------------------------------------------------
// K4: context += alpha . keys, n-split x4 (ctx zeroed in K1)
// ---------------------------------------------------------------------------
__global__ void context_kernel(const float* __restrict__ keys,
                               const float* __restrict__ alpha,
                               float* __restrict__ ctx) {
    const int b = blockIdx.z, n0 = blockIdx.y * 256;
    const int d = blockIdx.x * 256 + threadIdx.x;
    const float* kb = keys + (size_t)b * N_SZ * D_SZ + (size_t)n0 * D_SZ + d;
    const float* ab = alpha + b * N_SZ + n0;
    float acc = 0.f;
    #pragma unroll 8
    for (int n = 0; n < 256; n++)
        acc += ab[n] * kb[(size_t)n * D_SZ];
    atomicAdd(&ctx[b * D_SZ + d], acc);
}

// ---------------------------------------------------------------------------
extern "C" void kernel_launch(void* const* d_in, const int* in_sizes, int n_in,
                              void* d_out, int out_size) {
    const float* h_t  = (const float*)d_in[0];
    const float* keys = (const float*)d_in[1];
    const float* W_h  = (const float*)d_in[2];
    const float* W_k  = (const float*)d_in[3];
    const float* v    = (const float*)d_in[4];

    float* out   = (float*)d_out;
    float* ctx   = out;                  // context [64,1024]
    float* alpha = out + B_SZ * N_SZ;    // alpha   [64,1024]

    cudaFuncSetAttribute(score_tc, cudaFuncAttributeMaxDynamicSharedMemorySize,
                         TOT_W * 4);

    qh_kernel<<<dim3(4, B_SZ), 256>>>(h_t, W_h, ctx);
    score_tc<<<dim3(4, M_SZ / 128), 512, TOT_W * 4>>>(keys, W_k, v);
    softmax_kernel<<<B_SZ, 256>>>(alpha);
    context_kernel<<<dim3(4, 4, B_SZ), 256>>>(keys, alpha, ctx);
}

// round 9
// speedup vs baseline: 3.7890x; 1.3868x over previous
#include <cuda_runtime.h>
#include <cuda_fp16.h>
#include <math.h>

#define B_SZ 64
#define N_SZ 1024
#define D_SZ 1024
#define M_SZ (B_SZ * N_SZ)

__device__ float g_qh[B_SZ * D_SZ];
__device__ float g_part[4 * M_SZ];   // per-e-tile score partials

// ---------------- helpers --------------------------------------------------
__device__ __forceinline__ float tanh_fast(float x) {
    float e;
    asm("ex2.approx.f32 %0, %1;" : "=f"(e) : "f"(x * 2.885390082f));
    float r;
    asm("rcp.approx.f32 %0, %1;" : "=f"(r) : "f"(e + 1.0f));
    return fmaf(-2.0f, r, 1.0f);
}
__device__ __forceinline__ unsigned pack2(float lo, float hi) {
    __half2 h = __floats2half2_rn(lo, hi);   // .x = lo (low half)
    return *(unsigned*)&h;
}
__device__ __forceinline__ uint4 pack8(float4 u, float4 v) {
    uint4 r;
    r.x = pack2(u.x, u.y); r.y = pack2(u.z, u.w);
    r.z = pack2(v.x, v.y); r.w = pack2(v.z, v.w);
    return r;
}
#define MMA_F16(c, a, b0, b1) \
    asm volatile("mma.sync.aligned.m16n8k16.row.col.f32.f16.f16.f32 " \
        "{%0,%1,%2,%3}, {%4,%5,%6,%7}, {%8,%9}, {%0,%1,%2,%3};" \
        : "+f"((c)[0]), "+f"((c)[1]), "+f"((c)[2]), "+f"((c)[3]) \
        : "r"((a)[0]), "r"((a)[1]), "r"((a)[2]), "r"((a)[3]), \
          "r"(b0), "r"(b1))

// ---------------------------------------------------------------------------
// K1: qh[b,e] = h_t[b,:].W_h[e,:] (fp32); zero-init ctx slice.
// ---------------------------------------------------------------------------
__global__ void qh_kernel(const float* __restrict__ h_t,
                          const float* __restrict__ W_h,
                          float* __restrict__ ctx) {
    __shared__ float sh[D_SZ];
    const int b = blockIdx.y, es = blockIdx.x * 256;
    for (int d = threadIdx.x; d < D_SZ; d += 256)
        sh[d] = h_t[b * D_SZ + d];
    ctx[b * D_SZ + es + threadIdx.x] = 0.f;
    __syncthreads();
    const int warp = threadIdx.x >> 5, lane = threadIdx.x & 31;
    for (int e = es + warp; e < es + 256; e += 8) {
        const float* w = W_h + (size_t)e * D_SZ;
        float s = 0.f;
        #pragma unroll 8
        for (int d = lane; d < D_SZ; d += 32) s += sh[d] * w[d];
        #pragma unroll
        for (int off = 16; off; off >>= 1)
            s += __shfl_xor_sync(0xffffffffu, s, off);
        if (lane == 0) g_qh[b * D_SZ + e] = s;
    }
}

// ---------------------------------------------------------------------------
// K2: fused score GEMM, fp16 mma.sync m16n8k16 (fp32 accum).
// Tile 128m x 256e, 16 warps (4m x 4e), warp tile 32m x 64e, k-chunk 64,
// double-buffered SMEM. Words hold packed fp16 k-pairs; row pitch 36 words
// (conflict-free fragment LDS, identical index pattern to tf32 m16n8k8).
// ---------------------------------------------------------------------------
#define P 36
#define AW (128 * P)               // 4608 words
#define BW (256 * P)               // 9216 words
#define STAGE_W (AW + BW)          // 13824 words
#define SQ_W (2 * STAGE_W)
#define SV_W (SQ_W + 256)
#define SP_W (SV_W + 256)
#define TOT_W (SP_W + 128)         // 28288 words = 113152 bytes

__global__ void __launch_bounds__(512, 1)
score_tc(const float* __restrict__ keys,
         const float* __restrict__ W_k,
         const float* __restrict__ v) {
    extern __shared__ float sm[];
    unsigned* smw = (unsigned*)sm;
    const int tid = threadIdx.x;
    const int lane = tid & 31, warp = tid >> 5;
    const int g = lane >> 2, tg = lane & 3;
    const int mw = warp & 3, ew = warp >> 2;
    const int et = blockIdx.x, e0 = et * 256;
    const int m0 = blockIdx.y * 128, batch = m0 >> 10;

    // staging: thread owns rows (tid>>3)+64i, k-quad q=(tid&7) (8 floats)
    const int srow = tid >> 3;
    const int q8 = (tid & 7) * 8;
    const float* aR0 = keys + (size_t)(m0 + srow) * D_SZ + q8;
    const float* aR1 = aR0 + (size_t)64 * D_SZ;
    const float* bR0 = W_k + (size_t)(e0 + srow) * D_SZ + q8;
    const float* bR1 = bR0 + (size_t)64 * D_SZ;
    const float* bR2 = bR0 + (size_t)128 * D_SZ;
    const float* bR3 = bR0 + (size_t)192 * D_SZ;
    const int wA0 = srow * P + (tid & 7) * 4;       // word offsets, 16B aligned
    const int wA1 = wA0 + 64 * P;

    if (tid < 128) sm[SP_W + tid] = 0.f;
    if (tid < 256) sm[SQ_W + tid] = g_qh[batch * D_SZ + e0 + tid];
    else           sm[SV_W + tid - 256] = v[e0 + tid - 256];

    float acc[2][8][4];
    #pragma unroll
    for (int mt = 0; mt < 2; mt++)
        #pragma unroll
        for (int nt = 0; nt < 8; nt++)
            #pragma unroll
            for (int i = 0; i < 4; i++) acc[mt][nt][i] = 0.f;

    // prologue: chunk 0 -> stage 0
    uint4 stg[6];
    stg[0] = pack8(*(const float4*)aR0, *(const float4*)(aR0 + 4));
    stg[1] = pack8(*(const float4*)aR1, *(const float4*)(aR1 + 4));
    stg[2] = pack8(*(const float4*)bR0, *(const float4*)(bR0 + 4));
    stg[3] = pack8(*(const float4*)bR1, *(const float4*)(bR1 + 4));
    stg[4] = pack8(*(const float4*)bR2, *(const float4*)(bR2 + 4));
    stg[5] = pack8(*(const float4*)bR3, *(const float4*)(bR3 + 4));
    *(uint4*)(smw + wA0) = stg[0];
    *(uint4*)(smw + wA1) = stg[1];
    *(uint4*)(smw + AW + wA0) = stg[2];
    *(uint4*)(smw + AW + wA1) = stg[3];
    *(uint4*)(smw + AW + wA0 + 128 * P) = stg[4];
    *(uint4*)(smw + AW + wA1 + 128 * P) = stg[5];
    __syncthreads();

    const int aBase = (mw * 32 + g) * P + tg;
    const int bBase = (ew * 64 + g) * P + tg;

    for (int kb = 0; kb < 16; kb++) {
        const int s = kb & 1;
        if (kb < 15) {                               // prefetch + convert
            const int ko = (kb + 1) * 64;
            stg[0] = pack8(*(const float4*)(aR0 + ko), *(const float4*)(aR0 + ko + 4));
            stg[1] = pack8(*(const float4*)(aR1 + ko), *(const float4*)(aR1 + ko + 4));
            stg[2] = pack8(*(const float4*)(bR0 + ko), *(const float4*)(bR0 + ko + 4));
            stg[3] = pack8(*(const float4*)(bR1 + ko), *(const float4*)(bR1 + ko + 4));
            stg[4] = pack8(*(const float4*)(bR2 + ko), *(const float4*)(bR2 + ko + 4));
            stg[5] = pack8(*(const float4*)(bR3 + ko), *(const float4*)(bR3 + ko + 4));
        }
        {
            const unsigned* uA = smw + s * STAGE_W;
            const unsigned* uB = uA + AW;
            #pragma unroll
            for (int ks = 0; ks < 4; ks++) {         // k-step = 16 fp16 = 8 words
                const int ak = ks * 8;
                unsigned a[2][4];
                #pragma unroll
                for (int mt = 0; mt < 2; mt++) {
                    const int r = aBase + mt * 16 * P + ak;
                    a[mt][0] = uA[r];
                    a[mt][1] = uA[r + 8 * P];
                    a[mt][2] = uA[r + 4];
                    a[mt][3] = uA[r + 8 * P + 4];
                }
                #pragma unroll
                for (int nt = 0; nt < 8; nt++) {
                    const int bo = bBase + nt * 8 * P + ak;
                    unsigned b0 = uB[bo];
                    unsigned b1 = uB[bo + 4];
                    MMA_F16(acc[0][nt], a[0], b0, b1);
                    MMA_F16(acc[1][nt], a[1], b0, b1);
                }
            }
        }
        if (kb < 15) {
            unsigned* st = smw + (s ^ 1) * STAGE_W;
            *(uint4*)(st + wA0) = stg[0];
            *(uint4*)(st + wA1) = stg[1];
            *(uint4*)(st + AW + wA0) = stg[2];
            *(uint4*)(st + AW + wA1) = stg[3];
            *(uint4*)(st + AW + wA0 + 128 * P) = stg[4];
            *(uint4*)(st + AW + wA1 + 128 * P) = stg[5];
        }
        __syncthreads();
    }

    // epilogue: per-row partial of sum_e v[e]*tanh(acc + qh[e])
    const float* sQ = sm + SQ_W;
    const float* sV = sm + SV_W;
    #pragma unroll
    for (int mt = 0; mt < 2; mt++) {
        float s0 = 0.f, s1 = 0.f;
        #pragma unroll
        for (int nt = 0; nt < 8; nt++) {
            const int cb = ew * 64 + nt * 8 + 2 * tg;
            const float q0 = sQ[cb], q1 = sQ[cb + 1];
            const float v0 = sV[cb], v1 = sV[cb + 1];
            s0 += v0 * tanh_fast(acc[mt][nt][0] + q0)
                + v1 * tanh_fast(acc[mt][nt][1] + q1);
            s1 += v0 * tanh_fast(acc[mt][nt][2] + q0)
                + v1 * tanh_fast(acc[mt][nt][3] + q1);
        }
        #pragma unroll
        for (int off = 1; off <= 2; off <<= 1) {
            s0 += __shfl_xor_sync(0xffffffffu, s0, off);
            s1 += __shfl_xor_sync(0xffffffffu, s1, off);
        }
        if (tg == 0) {
            atomicAdd(&sm[SP_W + mw * 32 + mt * 16 + g], s0);
            atomicAdd(&sm[SP_W + mw * 32 + mt * 16 + 8 + g], s1);
        }
    }
    __syncthreads();
    if (tid < 128)
        g_part[et * M_SZ + m0 + tid] = sm[SP_W + tid];
}

// ---------------------------------------------------------------------------
// K3: softmax over summed partials -> alpha
// ---------------------------------------------------------------------------
__global__ void softmax_kernel(float* __restrict__ alpha) {
    const int b = blockIdx.x, tid = threadIdx.x;
    __shared__ float red[8];
    __shared__ float bcast;
    float x[4]; float m = -1e30f;
    #pragma unroll
    for (int i = 0; i < 4; i++) {
        const int idx = b * N_SZ + tid + i * 256;
        x[i] = g_part[idx] + g_part[M_SZ + idx]
             + g_part[2 * M_SZ + idx] + g_part[3 * M_SZ + idx];
        m = fmaxf(m, x[i]);
    }
    #pragma unroll
    for (int off = 16; off; off >>= 1)
        m = fmaxf(m, __shfl_xor_sync(0xffffffffu, m, off));
    if ((tid & 31) == 0) red[tid >> 5] = m;
    __syncthreads();
    if (tid == 0) {
        float mm = red[0];
        for (int w = 1; w < 8; w++) mm = fmaxf(mm, red[w]);
        bcast = mm;
    }
    __syncthreads();
    m = bcast;
    float s = 0.f;
    #pragma unroll
    for (int i = 0; i < 4; i++) { x[i] = expf(x[i] - m); s += x[i]; }
    #pragma unroll
    for (int off = 16; off; off >>= 1)
        s += __shfl_xor_sync(0xffffffffu, s, off);
    __syncthreads();
    if ((tid & 31) == 0) red[tid >> 5] = s;
    __syncthreads();
    if (tid == 0) {
        float ss = red[0];
        for (int w = 1; w < 8; w++) ss += red[w];
        bcast = ss;
    }
    __syncthreads();
    const float inv = 1.f / bcast;
    #pragma unroll
    for (int i = 0; i < 4; i++)
        alpha[b * N_SZ + tid + i * 256] = x[i] * inv;
}

// ---------------------------------------------------------------------------
// K4: context += alpha . keys, float4 per thread, n-split x8
// ---------------------------------------------------------------------------
__global__ void context_kernel(const float* __restrict__ keys,
                               const float* __restrict__ alpha,
                               float* __restrict__ ctx) {
    const int b = blockIdx.y, n0 = blockIdx.x * 128;
    const int d4 = threadIdx.x;                      // 256 float4 = 1024 d
    const float4* kb = (const float4*)(keys + (size_t)(b * N_SZ + n0) * D_SZ) + d4;
    const float* ab = alpha + b * N_SZ + n0;
    float4 acc = make_float4(0.f, 0.f, 0.f, 0.f);
    #pragma unroll 8
    for (int n = 0; n < 128; n++) {
        const float a = ab[n];
        const float4 k = kb[(size_t)n * (D_SZ / 4)];
        acc.x += a * k.x; acc.y += a * k.y;
        acc.z += a * k.z; acc.w += a * k.w;
    }
    float* o = ctx + b * D_SZ + d4 * 4;
    atomicAdd(o + 0, acc.x);
    atomicAdd(o + 1, acc.y);
    atomicAdd(o + 2, acc.z);
    atomicAdd(o + 3, acc.w);
}

// ---------------------------------------------------------------------------
extern "C" void kernel_launch(void* const* d_in, const int* in_sizes, int n_in,
                              void* d_out, int out_size) {
    const float* h_t  = (const float*)d_in[0];
    const float* keys = (const float*)d_in[1];
    const float* W_h  = (const float*)d_in[2];
    const float* W_k  = (const float*)d_in[3];
    const float* v    = (const float*)d_in[4];

    float* out   = (float*)d_out;
    float* ctx   = out;                  // context [64,1024]
    float* alpha = out + B_SZ * N_SZ;    // alpha   [64,1024]

    cudaFuncSetAttribute(score_tc, cudaFuncAttributeMaxDynamicSharedMemorySize,
                         TOT_W * 4);

    qh_kernel<<<dim3(4, B_SZ), 256>>>(h_t, W_h, ctx);
    score_tc<<<dim3(4, M_SZ / 128), 512, TOT_W * 4>>>(keys, W_k, v);
    softmax_kernel<<<B_SZ, 256>>>(alpha);
    context_kernel<<<dim3(8, B_SZ), 256>>>(keys, alpha, ctx);
}

// round 10
// speedup vs baseline: 4.5741x; 1.2072x over previous
#include <cuda_runtime.h>
#include <cuda_fp16.h>
#include <math.h>

#define B_SZ 64
#define N_SZ 1024
#define D_SZ 1024
#define M_SZ (B_SZ * N_SZ)

__device__ float g_qh[B_SZ * D_SZ];
__device__ float g_part[4 * M_SZ];
__device__ __half g_k16[(size_t)M_SZ * D_SZ];    // keys in fp16
__device__ __half g_w16[(size_t)D_SZ * D_SZ];    // W_k in fp16

// ---------------- helpers --------------------------------------------------
__device__ __forceinline__ float tanh_fast(float x) {
    float e;
    asm("ex2.approx.f32 %0, %1;" : "=f"(e) : "f"(x * 2.885390082f));
    float r;
    asm("rcp.approx.f32 %0, %1;" : "=f"(r) : "f"(e + 1.0f));
    return fmaf(-2.0f, r, 1.0f);
}
__device__ __forceinline__ unsigned pack2(float lo, float hi) {
    __half2 h = __floats2half2_rn(lo, hi);
    return *(unsigned*)&h;
}
__device__ __forceinline__ uint4 pack8(float4 u, float4 v) {
    uint4 r;
    r.x = pack2(u.x, u.y); r.y = pack2(u.z, u.w);
    r.z = pack2(v.x, v.y); r.w = pack2(v.z, v.w);
    return r;
}
__device__ __forceinline__ unsigned smem_u32(const void* p) {
    unsigned a;
    asm("{ .reg .u64 t; cvta.to.shared.u64 t, %1; cvt.u32.u64 %0, t; }"
        : "=r"(a) : "l"(p));
    return a;
}
#define MMA_F16(c, a, b0, b1) \
    asm volatile("mma.sync.aligned.m16n8k16.row.col.f32.f16.f16.f32 " \
        "{%0,%1,%2,%3}, {%4,%5,%6,%7}, {%8,%9}, {%0,%1,%2,%3};" \
        : "+f"((c)[0]), "+f"((c)[1]), "+f"((c)[2]), "+f"((c)[3]) \
        : "r"((a)[0]), "r"((a)[1]), "r"((a)[2]), "r"((a)[3]), \
          "r"(b0), "r"(b1))
#define LDM4(r, addr) \
    asm volatile("ldmatrix.sync.aligned.m8n8.x4.shared.b16 {%0,%1,%2,%3}, [%4];" \
        : "=r"((r)[0]), "=r"((r)[1]), "=r"((r)[2]), "=r"((r)[3]) : "r"(addr))
#define CP16(d, s) \
    asm volatile("cp.async.cg.shared.global [%0], [%1], 16;" \
        :: "r"(d), "l"(s) : "memory")
#define CPCOMMIT() asm volatile("cp.async.commit_group;" ::: "memory")
#define CPWAIT(n)  asm volatile("cp.async.wait_group %0;" :: "n"(n) : "memory")

// ---------------------------------------------------------------------------
// K0: fp32 -> fp16 conversion (keys, W_k)
// ---------------------------------------------------------------------------
__global__ void conv_keys(const float4* __restrict__ src) {
    size_t i = (size_t)blockIdx.x * 256 + threadIdx.x;
    ((uint4*)g_k16)[i] = pack8(src[2 * i], src[2 * i + 1]);
}
__global__ void conv_wk(const float4* __restrict__ src) {
    size_t i = (size_t)blockIdx.x * 256 + threadIdx.x;
    ((uint4*)g_w16)[i] = pack8(src[2 * i], src[2 * i + 1]);
}

// ---------------------------------------------------------------------------
// K1: qh[b,e] = h_t[b,:].W_h[e,:] (fp32); zero-init ctx slice.
// ---------------------------------------------------------------------------
__global__ void qh_kernel(const float* __restrict__ h_t,
                          const float* __restrict__ W_h,
                          float* __restrict__ ctx) {
    __shared__ float sh[D_SZ];
    const int b = blockIdx.y, es = blockIdx.x * 256;
    for (int d = threadIdx.x; d < D_SZ; d += 256)
        sh[d] = h_t[b * D_SZ + d];
    ctx[b * D_SZ + es + threadIdx.x] = 0.f;
    __syncthreads();
    const int warp = threadIdx.x >> 5, lane = threadIdx.x & 31;
    for (int e = es + warp; e < es + 256; e += 8) {
        const float* w = W_h + (size_t)e * D_SZ;
        float s = 0.f;
        #pragma unroll 8
        for (int d = lane; d < D_SZ; d += 32) s += sh[d] * w[d];
        #pragma unroll
        for (int off = 16; off; off >>= 1)
            s += __shfl_xor_sync(0xffffffffu, s, off);
        if (lane == 0) g_qh[b * D_SZ + e] = s;
    }
}

// ---------------------------------------------------------------------------
// K2: fused score GEMM: fp16 mma.sync + cp.async 3-stage + ldmatrix.
// Tile 128m x 256e, 16 warps (4m x 4e), warp tile 32m x 64e, k-chunk 64.
// SMEM rows pitch 144B (72 fp16): conflict-free ldmatrix, aligned cp.async.
// Stage: A 128x144B = 18432, B 256x144B = 36864 -> 55296 B; 3 stages.
// ---------------------------------------------------------------------------
#define PITCH_B 144
#define A_BYTES 18432
#define STG_BYTES 55296
#define SQ_F 41472                 // float index: 3*55296/4
#define SV_F (SQ_F + 256)
#define SP_F (SV_F + 256)
#define SM_BYTES (3 * STG_BYTES + 2560)

__global__ void __launch_bounds__(512, 1)
score_tc(const float* __restrict__ v) {
    extern __shared__ float smf[];
    const unsigned sb = smem_u32(smf);
    const int tid = threadIdx.x;
    const int lane = tid & 31, warp = tid >> 5;
    const int g = lane >> 2, tg = lane & 3;
    const int mw = warp & 3, ew = warp >> 2;
    const int et = blockIdx.x, e0 = et * 256;
    const int m0 = blockIdx.y * 128, batch = m0 >> 10;

    if (tid < 128) smf[SP_F + tid] = 0.f;
    if (tid < 256) smf[SQ_F + tid] = g_qh[batch * D_SZ + e0 + tid];
    else           smf[SV_F + tid - 256] = v[e0 + tid - 256];

    // cp.async geometry: thread owns rows srow+64i, 16B chunk q of the
    // 64-fp16 (128B) k-chunk row.
    const int srow = tid >> 3, q = tid & 7;
    const __half* sA0 = g_k16 + (size_t)(m0 + srow) * D_SZ + q * 8;
    const __half* sA1 = sA0 + (size_t)64 * D_SZ;
    const __half* sB0 = g_w16 + (size_t)(e0 + srow) * D_SZ + q * 8;
    const __half* sB1 = sB0 + (size_t)64 * D_SZ;
    const __half* sB2 = sB0 + (size_t)128 * D_SZ;
    const __half* sB3 = sB0 + (size_t)192 * D_SZ;
    const unsigned dA0 = srow * PITCH_B + q * 16;
    const unsigned dA1 = dA0 + 64 * PITCH_B;
    const unsigned dB0 = A_BYTES + srow * PITCH_B + q * 16;
    const unsigned dB1 = dB0 + 64 * PITCH_B;
    const unsigned dB2 = dB0 + 128 * PITCH_B;
    const unsigned dB3 = dB0 + 192 * PITCH_B;

    // ldmatrix lane offsets (bytes)
    const unsigned aLM = (mw * 32 + (lane & 15)) * PITCH_B + (lane >> 4) * 16;
    const unsigned bLM = A_BYTES
        + (ew * 64 + (lane & 7) + ((lane >> 4) & 1) * 8) * PITCH_B
        + ((lane >> 3) & 1) * 16;

    float acc[2][8][4];
    #pragma unroll
    for (int mt = 0; mt < 2; mt++)
        #pragma unroll
        for (int nt = 0; nt < 8; nt++)
            #pragma unroll
            for (int i = 0; i < 4; i++) acc[mt][nt][i] = 0.f;

    #define ISSUE(kb, s) do { \
        const unsigned bs = sb + (s) * STG_BYTES; \
        const int ko = (kb) * 64; \
        CP16(bs + dA0, sA0 + ko); CP16(bs + dA1, sA1 + ko); \
        CP16(bs + dB0, sB0 + ko); CP16(bs + dB1, sB1 + ko); \
        CP16(bs + dB2, sB2 + ko); CP16(bs + dB3, sB3 + ko); \
    } while (0)

    ISSUE(0, 0); CPCOMMIT();
    ISSUE(1, 1); CPCOMMIT();

    for (int kb = 0; kb < 16; kb++) {
        if (kb < 14) { CPWAIT(1); } else { CPWAIT(0); }
        __syncthreads();
        if (kb + 2 < 16) {
            int s2 = kb + 2; s2 = (s2 >= 3) ? ((s2 >= 6) ? ((s2 >= 9) ? ((s2 >= 12) ? ((s2 >= 15) ? s2 - 15 : s2 - 12) : s2 - 9) : s2 - 6) : s2 - 3) : s2;
            ISSUE(kb + 2, s2);
            CPCOMMIT();
        }
        {
            int s = kb; s = (s >= 3) ? ((s >= 6) ? ((s >= 9) ? ((s >= 12) ? ((s >= 15) ? s - 15 : s - 12) : s - 9) : s - 6) : s - 3) : s;
            const unsigned stA = sb + s * STG_BYTES;
            #pragma unroll
            for (int ks = 0; ks < 4; ks++) {
                const unsigned ko = ks * 32;
                unsigned a0[4], a1[4];
                LDM4(a0, stA + aLM + ko);
                LDM4(a1, stA + aLM + 16 * PITCH_B + ko);
                #pragma unroll
                for (int ntp = 0; ntp < 4; ntp++) {
                    unsigned bf[4];
                    LDM4(bf, stA + bLM + ntp * 16 * PITCH_B + ko);
                    MMA_F16(acc[0][2 * ntp],     a0, bf[0], bf[1]);
                    MMA_F16(acc[0][2 * ntp + 1], a0, bf[2], bf[3]);
                    MMA_F16(acc[1][2 * ntp],     a1, bf[0], bf[1]);
                    MMA_F16(acc[1][2 * ntp + 1], a1, bf[2], bf[3]);
                }
            }
        }
    }
    __syncthreads();

    // epilogue: per-row partial of sum_e v[e]*tanh(acc + qh[e])
    const float* sQ = smf + SQ_F;
    const float* sV = smf + SV_F;
    #pragma unroll
    for (int mt = 0; mt < 2; mt++) {
        float s0 = 0.f, s1 = 0.f;
        #pragma unroll
        for (int nt = 0; nt < 8; nt++) {
            const int cb = ew * 64 + nt * 8 + 2 * tg;
            const float q0 = sQ[cb], q1 = sQ[cb + 1];
            const float v0 = sV[cb], v1 = sV[cb + 1];
            s0 += v0 * tanh_fast(acc[mt][nt][0] + q0)
                + v1 * tanh_fast(acc[mt][nt][1] + q1);
            s1 += v0 * tanh_fast(acc[mt][nt][2] + q0)
                + v1 * tanh_fast(acc[mt][nt][3] + q1);
        }
        #pragma unroll
        for (int off = 1; off <= 2; off <<= 1) {
            s0 += __shfl_xor_sync(0xffffffffu, s0, off);
            s1 += __shfl_xor_sync(0xffffffffu, s1, off);
        }
        if (tg == 0) {
            atomicAdd(&smf[SP_F + mw * 32 + mt * 16 + g], s0);
            atomicAdd(&smf[SP_F + mw * 32 + mt * 16 + 8 + g], s1);
        }
    }
    __syncthreads();
    if (tid < 128)
        g_part[et * M_SZ + m0 + tid] = smf[SP_F + tid];
}

// ---------------------------------------------------------------------------
// K3: softmax over summed partials -> alpha
// ---------------------------------------------------------------------------
__global__ void softmax_kernel(float* __restrict__ alpha) {
    const int b = blockIdx.x, tid = threadIdx.x;
    __shared__ float red[8];
    __shared__ float bcast;
    float x[4]; float m = -1e30f;
    #pragma unroll
    for (int i = 0; i < 4; i++) {
        const int idx = b * N_SZ + tid + i * 256;
        x[i] = g_part[idx] + g_part[M_SZ + idx]
             + g_part[2 * M_SZ + idx] + g_part[3 * M_SZ + idx];
        m = fmaxf(m, x[i]);
    }
    #pragma unroll
    for (int off = 16; off; off >>= 1)
        m = fmaxf(m, __shfl_xor_sync(0xffffffffu, m, off));
    if ((tid & 31) == 0) red[tid >> 5] = m;
    __syncthreads();
    if (tid == 0) {
        float mm = red[0];
        for (int w = 1; w < 8; w++) mm = fmaxf(mm, red[w]);
        bcast = mm;
    }
    __syncthreads();
    m = bcast;
    float s = 0.f;
    #pragma unroll
    for (int i = 0; i < 4; i++) { x[i] = expf(x[i] - m); s += x[i]; }
    #pragma unroll
    for (int off = 16; off; off >>= 1)
        s += __shfl_xor_sync(0xffffffffu, s, off);
    __syncthreads();
    if ((tid & 31) == 0) red[tid >> 5] = s;
    __syncthreads();
    if (tid == 0) {
        float ss = red[0];
        for (int w = 1; w < 8; w++) ss += red[w];
        bcast = ss;
    }
    __syncthreads();
    const float inv = 1.f / bcast;
    #pragma unroll
    for (int i = 0; i < 4; i++)
        alpha[b * N_SZ + tid + i * 256] = x[i] * inv;
}

// ---------------------------------------------------------------------------
// K4: context += alpha . keys (fp32), float4 per thread, n-split x8
// ---------------------------------------------------------------------------
__global__ void context_kernel(const float* __restrict__ keys,
                               const float* __restrict__ alpha,
                               float* __restrict__ ctx) {
    const int b = blockIdx.y, n0 = blockIdx.x * 128;
    const int d4 = threadIdx.x;
    const float4* kb = (const float4*)(keys + (size_t)(b * N_SZ + n0) * D_SZ) + d4;
    const float* ab = alpha + b * N_SZ + n0;
    float4 acc = make_float4(0.f, 0.f, 0.f, 0.f);
    #pragma unroll 8
    for (int n = 0; n < 128; n++) {
        const float a = ab[n];
        const float4 k = kb[(size_t)n * (D_SZ / 4)];
        acc.x += a * k.x; acc.y += a * k.y;
        acc.z += a * k.z; acc.w += a * k.w;
    }
    float* o = ctx + b * D_SZ + d4 * 4;
    atomicAdd(o + 0, acc.x);
    atomicAdd(o + 1, acc.y);
    atomicAdd(o + 2, acc.z);
    atomicAdd(o + 3, acc.w);
}

// ---------------------------------------------------------------------------
extern "C" void kernel_launch(void* const* d_in, const int* in_sizes, int n_in,
                              void* d_out, int out_size) {
    const float* h_t  = (const float*)d_in[0];
    const float* keys = (const float*)d_in[1];
    const float* W_h  = (const float*)d_in[2];
    const float* W_k  = (const float*)d_in[3];
    const float* v    = (const float*)d_in[4];

    float* out   = (float*)d_out;
    float* ctx   = out;
    float* alpha = out + B_SZ * N_SZ;

    cudaFuncSetAttribute(score_tc, cudaFuncAttributeMaxDynamicSharedMemorySize,
                         SM_BYTES);

    conv_keys<<<(int)((size_t)M_SZ * D_SZ / 2048), 256>>>((const float4*)keys);
    conv_wk<<<D_SZ * D_SZ / 2048, 256>>>((const float4*)W_k);
    qh_kernel<<<dim3(4, B_SZ), 256>>>(h_t, W_h, ctx);
    score_tc<<<dim3(4, M_SZ / 128), 512, SM_BYTES>>>(v);
    softmax_kernel<<<B_SZ, 256>>>(alpha);
    context_kernel<<<dim3(8, B_SZ), 256>>>(keys, alpha, ctx);
}